// round 1
// baseline (speedup 1.0000x reference)
#include <cuda_runtime.h>
#include <math.h>

#define BATCH 4
#define C 128
#define MID 32
#define HW 64
#define N 4096   // HW*HW

// ---------------- static device scratch (no runtime allocation) ----------------
__device__ float g_Q[BATCH][C][N];        // query conv output (x2)
__device__ float g_V[BATCH][C][N];        // value conv output (x1)
__device__ float g_invnorm[BATCH][N];     // 1/max(||q_n||,1e-4)
__device__ float g_wmap[BATCH][N];        // weight head output
__device__ float g_bmap[BATCH][N];        // bias head output
__device__ float g_mean[BATCH][N];        // column mean of logits
__device__ float g_smax[BATCH][N];        // column max of z = l*sparse
__device__ float g_sinv[BATCH][N];        // 1/sum(exp(z-max))
__device__ float g_L[BATCH][N][N];        // logits [keys n][queries m]  (256MB)
__device__ float g_Ymid[BATCH][C][N];     // attention output before conv3x3

// ============================================================================
// K1: Q = q_w @ x + q_b ; V = v_w @ x + v_b   (1x1 convs as GEMM)
// tile 128(o) x 128(n), K=128, 256 threads, 8x8 per thread
// ============================================================================
__global__ void k1_qv(const float* __restrict__ x,
                      const float* __restrict__ qw, const float* __restrict__ qb,
                      const float* __restrict__ vw, const float* __restrict__ vb) {
    const int b = blockIdx.y;
    const int which = blockIdx.z;
    const float* W = which ? vw : qw;
    const float* bias = which ? vb : qb;
    float* out = which ? &g_V[b][0][0] : &g_Q[b][0][0];
    const int n0 = blockIdx.x * 128;
    const float* xb = x + (size_t)b * C * N;

    __shared__ float As[16][128];
    __shared__ float Bs[16][128];
    const int tid = threadIdx.x;
    const int tx = tid & 15, ty = tid >> 4;

    float acc[8][8];
#pragma unroll
    for (int i = 0; i < 8; i++)
#pragma unroll
        for (int j = 0; j < 8; j++) acc[i][j] = 0.f;

    for (int k0 = 0; k0 < 128; k0 += 16) {
        // As[k][o] = W[o*128 + k0+k]
        {
            int o = tid >> 1;
            int kb = (tid & 1) * 8;
            float4 a0 = *(const float4*)(W + o * 128 + k0 + kb);
            float4 a1 = *(const float4*)(W + o * 128 + k0 + kb + 4);
            As[kb + 0][o] = a0.x; As[kb + 1][o] = a0.y; As[kb + 2][o] = a0.z; As[kb + 3][o] = a0.w;
            As[kb + 4][o] = a1.x; As[kb + 5][o] = a1.y; As[kb + 6][o] = a1.z; As[kb + 7][o] = a1.w;
        }
        // Bs[k][n] = x[b][k0+k][n0+n]
        {
            int kk = tid >> 4;
            int nn = (tid & 15) * 8;
            float4 b0 = *(const float4*)(xb + (size_t)(k0 + kk) * N + n0 + nn);
            float4 b1 = *(const float4*)(xb + (size_t)(k0 + kk) * N + n0 + nn + 4);
            *(float4*)&Bs[kk][nn] = b0;
            *(float4*)&Bs[kk][nn + 4] = b1;
        }
        __syncthreads();
#pragma unroll
        for (int kk = 0; kk < 16; kk++) {
            float ra[8], rb[8];
            *(float4*)&ra[0] = *(const float4*)&As[kk][ty * 8];
            *(float4*)&ra[4] = *(const float4*)&As[kk][ty * 8 + 4];
            *(float4*)&rb[0] = *(const float4*)&Bs[kk][tx * 8];
            *(float4*)&rb[4] = *(const float4*)&Bs[kk][tx * 8 + 4];
#pragma unroll
            for (int i = 0; i < 8; i++)
#pragma unroll
                for (int j = 0; j < 8; j++)
                    acc[i][j] = fmaf(ra[i], rb[j], acc[i][j]);
        }
        __syncthreads();
    }
#pragma unroll
    for (int i = 0; i < 8; i++) {
        int o = ty * 8 + i;
        float bo = bias[o];
        float4 r0, r1;
        r0.x = acc[i][0] + bo; r0.y = acc[i][1] + bo; r0.z = acc[i][2] + bo; r0.w = acc[i][3] + bo;
        r1.x = acc[i][4] + bo; r1.y = acc[i][5] + bo; r1.z = acc[i][6] + bo; r1.w = acc[i][7] + bo;
        *(float4*)(out + (size_t)o * N + n0 + tx * 8) = r0;
        *(float4*)(out + (size_t)o * N + n0 + tx * 8 + 4) = r1;
    }
}

// ============================================================================
// K2: per-token heads (weight map, bias map) + inverse key norm
// one thread per token
// ============================================================================
__global__ void k2_heads(const float* __restrict__ lw1w, const float* __restrict__ lw1b,
                         const float* __restrict__ lw2w, const float* __restrict__ lw2b,
                         const float* __restrict__ bw1w, const float* __restrict__ bw1b,
                         const float* __restrict__ bw2w, const float* __restrict__ bw2b) {
    __shared__ float s_lw1[MID][C];
    __shared__ float s_bw1[MID][C];
    const int b = blockIdx.y;
    const int n = blockIdx.x * 256 + threadIdx.x;
    for (int e = threadIdx.x; e < MID * C; e += 256) {
        s_lw1[e / C][e % C] = lw1w[e];
        s_bw1[e / C][e % C] = bw1w[e];
    }
    __syncthreads();

    float hl[MID], hb[MID];
#pragma unroll
    for (int h = 0; h < MID; h++) { hl[h] = 0.f; hb[h] = 0.f; }
    float sq = 0.f;
#pragma unroll 4
    for (int c = 0; c < C; c++) {
        float q = g_Q[b][c][n];
        sq = fmaf(q, q, sq);
#pragma unroll
        for (int h = 0; h < MID; h++) {
            hl[h] = fmaf(s_lw1[h][c], q, hl[h]);
            hb[h] = fmaf(s_bw1[h][c], q, hb[h]);
        }
    }
    float wv = lw2b[0], bv = bw2b[0];
#pragma unroll
    for (int h = 0; h < MID; h++) {
        float t = hl[h] + lw1b[h];
        t = (t >= 0.f) ? t : 0.2f * t;
        wv = fmaf(lw2w[h], t, wv);
        float u = hb[h] + bw1b[h];
        u = (u >= 0.f) ? u : 0.2f * u;
        bv = fmaf(bw2w[h], u, bv);
    }
    g_wmap[b][n] = wv;
    g_bmap[b][n] = bv;
    g_invnorm[b][n] = 1.0f / fmaxf(sqrtf(sq), 1e-4f);
}

// ============================================================================
// K3: logits L[n][m] = (sum_c Q[c][n] * Q[c][m]) * invnorm[n]
// tile 128(n) x 128(m), K=128
// ============================================================================
__global__ void k3_logits() {
    const int b = blockIdx.z;
    const int m0 = blockIdx.x * 128;
    const int n0 = blockIdx.y * 128;

    __shared__ float As[16][128];
    __shared__ float Bs[16][128];
    const int tid = threadIdx.x;
    const int tx = tid & 15, ty = tid >> 4;

    float acc[8][8];
#pragma unroll
    for (int i = 0; i < 8; i++)
#pragma unroll
        for (int j = 0; j < 8; j++) acc[i][j] = 0.f;

    const int kk = tid >> 4;
    const int cc = (tid & 15) * 8;
    for (int k0 = 0; k0 < 128; k0 += 16) {
        float4 a0 = *(const float4*)&g_Q[b][k0 + kk][n0 + cc];
        float4 a1 = *(const float4*)&g_Q[b][k0 + kk][n0 + cc + 4];
        *(float4*)&As[kk][cc] = a0; *(float4*)&As[kk][cc + 4] = a1;
        float4 b0 = *(const float4*)&g_Q[b][k0 + kk][m0 + cc];
        float4 b1 = *(const float4*)&g_Q[b][k0 + kk][m0 + cc + 4];
        *(float4*)&Bs[kk][cc] = b0; *(float4*)&Bs[kk][cc + 4] = b1;
        __syncthreads();
#pragma unroll
        for (int k = 0; k < 16; k++) {
            float ra[8], rb[8];
            *(float4*)&ra[0] = *(const float4*)&As[k][ty * 8];
            *(float4*)&ra[4] = *(const float4*)&As[k][ty * 8 + 4];
            *(float4*)&rb[0] = *(const float4*)&Bs[k][tx * 8];
            *(float4*)&rb[4] = *(const float4*)&Bs[k][tx * 8 + 4];
#pragma unroll
            for (int i = 0; i < 8; i++)
#pragma unroll
                for (int j = 0; j < 8; j++)
                    acc[i][j] = fmaf(ra[i], rb[j], acc[i][j]);
        }
        __syncthreads();
    }
#pragma unroll
    for (int i = 0; i < 8; i++) {
        int n = n0 + ty * 8 + i;
        float inv = g_invnorm[b][n];
        float4 r0, r1;
        r0.x = acc[i][0] * inv; r0.y = acc[i][1] * inv; r0.z = acc[i][2] * inv; r0.w = acc[i][3] * inv;
        r1.x = acc[i][4] * inv; r1.y = acc[i][5] * inv; r1.z = acc[i][6] * inv; r1.w = acc[i][7] * inv;
        *(float4*)&g_L[b][n][m0 + tx * 8] = r0;
        *(float4*)&g_L[b][n][m0 + tx * 8 + 4] = r1;
    }
}

// ============================================================================
// K4: per-column stats: mean (pass 1), online max & sum-exp of z=l*sparse (pass 2)
// block = 32 columns x 8 row-slices
// ============================================================================
__global__ void k4_stats() {
    const int b = blockIdx.y;
    const int tx = threadIdx.x & 31;
    const int sy = threadIdx.x >> 5;
    const int m = blockIdx.x * 32 + tx;

    __shared__ float s0[8][32];
    __shared__ float s1[8][32];
    __shared__ float s_mean[32];

    // pass 1: column sum -> mean
    float part = 0.f;
#pragma unroll 4
    for (int n = sy; n < N; n += 8)
        part += g_L[b][n][m];
    s0[sy][tx] = part;
    __syncthreads();
    if (sy == 0) {
        float s = s0[0][tx];
#pragma unroll
        for (int r = 1; r < 8; r++) s += s0[r][tx];
        s_mean[tx] = s * (1.0f / N);
    }
    __syncthreads();

    const float mean = s_mean[tx];
    const float off = g_bmap[b][m] - mean * g_wmap[b][m];

    // pass 2: online max / sum-exp of z = l * relu(l + off)
    float mx = -1e30f, s = 0.f;
#pragma unroll 2
    for (int n = sy; n < N; n += 8) {
        float l = g_L[b][n][m];
        float sp = fmaxf(l + off, 0.f);
        float z = l * sp;
        float mn = fmaxf(mx, z);
        s = s * __expf(mx - mn) + __expf(z - mn);
        mx = mn;
    }
    s0[sy][tx] = mx;
    s1[sy][tx] = s;
    __syncthreads();
    if (sy == 0) {
        float M = s0[0][tx], S = s1[0][tx];
#pragma unroll
        for (int r = 1; r < 8; r++) {
            float m2 = s0[r][tx], sx = s1[r][tx];
            float Mn = fmaxf(M, m2);
            S = S * __expf(M - Mn) + sx * __expf(m2 - Mn);
            M = Mn;
        }
        g_mean[b][m] = mean;
        g_smax[b][m] = M;
        g_sinv[b][m] = 1.0f / S;
    }
}

// ============================================================================
// K5: Y = V @ attn(L)   -- attn computed on-the-fly from L + column params
// tile 128(c) x 128(m), K = N = 4096
// ============================================================================
__global__ void k5_out() {
    const int b = blockIdx.y;
    const int m0 = blockIdx.x * 128;

    __shared__ float As[16][128];
    __shared__ float Bs[16][128];
    __shared__ float p_off[128], p_mx[128], p_si[128];
    const int tid = threadIdx.x;
    const int tx = tid & 15, ty = tid >> 4;

    if (tid < 128) {
        int m = m0 + tid;
        p_off[tid] = g_bmap[b][m] - g_mean[b][m] * g_wmap[b][m];
        p_mx[tid] = g_smax[b][m];
        p_si[tid] = g_sinv[b][m];
    }
    __syncthreads();

    float acc[8][8];
#pragma unroll
    for (int i = 0; i < 8; i++)
#pragma unroll
        for (int j = 0; j < 8; j++) acc[i][j] = 0.f;

    const int ac = tid >> 1;
    const int akb = (tid & 1) * 8;
    const int bkk = tid >> 4;
    const int bmm = (tid & 15) * 8;

    for (int n0 = 0; n0 < N; n0 += 16) {
        // As[kk][c] = V[c][n0+kk]
        {
            float4 a0 = *(const float4*)&g_V[b][ac][n0 + akb];
            float4 a1 = *(const float4*)&g_V[b][ac][n0 + akb + 4];
            As[akb + 0][ac] = a0.x; As[akb + 1][ac] = a0.y; As[akb + 2][ac] = a0.z; As[akb + 3][ac] = a0.w;
            As[akb + 4][ac] = a1.x; As[akb + 5][ac] = a1.y; As[akb + 6][ac] = a1.z; As[akb + 7][ac] = a1.w;
        }
        // Bs[kk][mm] = attn(L[n0+kk][m0+mm])
        {
            float lv[8];
            *(float4*)&lv[0] = *(const float4*)&g_L[b][n0 + bkk][m0 + bmm];
            *(float4*)&lv[4] = *(const float4*)&g_L[b][n0 + bkk][m0 + bmm + 4];
#pragma unroll
            for (int j = 0; j < 8; j++) {
                int m = bmm + j;
                float l = lv[j];
                float sp = fmaxf(l + p_off[m], 0.f);
                float a;
                if (sp > 0.f)
                    a = fmaxf(__expf(l * sp - p_mx[m]) * p_si[m], 1e-8f);
                else
                    a = 1e-8f;
                Bs[bkk][m] = a;
            }
        }
        __syncthreads();
#pragma unroll
        for (int k = 0; k < 16; k++) {
            float ra[8], rb[8];
            *(float4*)&ra[0] = *(const float4*)&As[k][ty * 8];
            *(float4*)&ra[4] = *(const float4*)&As[k][ty * 8 + 4];
            *(float4*)&rb[0] = *(const float4*)&Bs[k][tx * 8];
            *(float4*)&rb[4] = *(const float4*)&Bs[k][tx * 8 + 4];
#pragma unroll
            for (int i = 0; i < 8; i++)
#pragma unroll
                for (int j = 0; j < 8; j++)
                    acc[i][j] = fmaf(ra[i], rb[j], acc[i][j]);
        }
        __syncthreads();
    }
#pragma unroll
    for (int i = 0; i < 8; i++) {
        int c = ty * 8 + i;
        *(float4*)&g_Ymid[b][c][m0 + tx * 8] = *(float4*)&acc[i][0];
        *(float4*)&g_Ymid[b][c][m0 + tx * 8 + 4] = *(float4*)&acc[i][4];
    }
}

// ============================================================================
// K6: conv3x3(SAME) as 9 shifted GEMMs + bias + leaky + residual
// tile 128(o) x 128(px), K = 9*128
// ============================================================================
__global__ void k6_conv(const float* __restrict__ linw, const float* __restrict__ linb,
                        const float* __restrict__ x, float* __restrict__ out) {
    const int b = blockIdx.y;
    const int p0 = blockIdx.x * 128;

    __shared__ float As[16][128];
    __shared__ float Bs[16][128];
    const int tid = threadIdx.x;
    const int tx = tid & 15, ty = tid >> 4;

    float acc[8][8];
#pragma unroll
    for (int i = 0; i < 8; i++)
#pragma unroll
        for (int j = 0; j < 8; j++) acc[i][j] = 0.f;

    const int ao = tid >> 1;
    const int akb = (tid & 1) * 8;
    const int bkk = tid >> 4;
    const int bpx = (tid & 15) * 8;

    for (int t = 0; t < 9; t++) {
        const int dh = t / 3 - 1, dw = t % 3 - 1;
        for (int i0 = 0; i0 < 128; i0 += 16) {
            // As[kk][o] = linw[(o*128 + i0+kk)*9 + t]
#pragma unroll
            for (int q = 0; q < 8; q++)
                As[akb + q][ao] = linw[(size_t)(ao * 128 + i0 + akb + q) * 9 + t];
            // Bs[kk][px] = shifted Ymid with zero padding
#pragma unroll
            for (int q = 0; q < 8; q++) {
                int p = p0 + bpx + q;
                int h = p >> 6, w = p & 63;
                int hh = h + dh, ww = w + dw;
                float v = 0.f;
                if (hh >= 0 && hh < HW && ww >= 0 && ww < HW)
                    v = g_Ymid[b][i0 + bkk][(hh << 6) + ww];
                Bs[bkk][bpx + q] = v;
            }
            __syncthreads();
#pragma unroll
            for (int k = 0; k < 16; k++) {
                float ra[8], rb[8];
                *(float4*)&ra[0] = *(const float4*)&As[k][ty * 8];
                *(float4*)&ra[4] = *(const float4*)&As[k][ty * 8 + 4];
                *(float4*)&rb[0] = *(const float4*)&Bs[k][tx * 8];
                *(float4*)&rb[4] = *(const float4*)&Bs[k][tx * 8 + 4];
#pragma unroll
                for (int i = 0; i < 8; i++)
#pragma unroll
                    for (int j = 0; j < 8; j++)
                        acc[i][j] = fmaf(ra[i], rb[j], acc[i][j]);
            }
            __syncthreads();
        }
    }
#pragma unroll
    for (int i = 0; i < 8; i++) {
        int o = ty * 8 + i;
        float bo = linb[o];
        size_t base = ((size_t)b * C + o) * N + p0 + tx * 8;
#pragma unroll
        for (int j = 0; j < 8; j++) {
            float v = acc[i][j] + bo;
            v = (v >= 0.f) ? v : 0.2f * v;
            out[base + j] = v + x[base + j];
        }
    }
}

// ============================================================================
extern "C" void kernel_launch(void* const* d_in, const int* in_sizes, int n_in,
                              void* d_out, int out_size) {
    const float* x     = (const float*)d_in[0];
    const float* q_w   = (const float*)d_in[1];
    const float* q_b   = (const float*)d_in[2];
    const float* v_w   = (const float*)d_in[3];
    const float* v_b   = (const float*)d_in[4];
    const float* lw1_w = (const float*)d_in[5];
    const float* lw1_b = (const float*)d_in[6];
    const float* lw2_w = (const float*)d_in[7];
    const float* lw2_b = (const float*)d_in[8];
    const float* bw1_w = (const float*)d_in[9];
    const float* bw1_b = (const float*)d_in[10];
    const float* bw2_w = (const float*)d_in[11];
    const float* bw2_b = (const float*)d_in[12];
    const float* lin_w = (const float*)d_in[13];
    const float* lin_b = (const float*)d_in[14];
    float* out = (float*)d_out;

    k1_qv<<<dim3(N / 128, BATCH, 2), 256>>>(x, q_w, q_b, v_w, v_b);
    k2_heads<<<dim3(N / 256, BATCH), 256>>>(lw1_w, lw1_b, lw2_w, lw2_b,
                                            bw1_w, bw1_b, bw2_w, bw2_b);
    k3_logits<<<dim3(N / 128, N / 128, BATCH), 256>>>();
    k4_stats<<<dim3(N / 32, BATCH), 256>>>();
    k5_out<<<dim3(N / 128, BATCH), 256>>>();
    k6_conv<<<dim3(N / 128, BATCH), 256>>>(lin_w, lin_b, x, out);
}

// round 2
// speedup vs baseline: 1.2320x; 1.2320x over previous
#include <cuda_runtime.h>
#include <math.h>

#define BATCH 4
#define C 128
#define MID 32
#define HW 64
#define N 4096   // HW*HW

// ---------------- static device scratch (no runtime allocation) ----------------
__device__ float g_Q[BATCH][C][N];        // query conv output (x2)
__device__ float g_V[BATCH][C][N];        // value conv output (x1)
__device__ float g_invnorm[BATCH][N];     // 1/max(||q_n||,1e-4)
__device__ float g_wmap[BATCH][N];        // weight head output
__device__ float g_bmap[BATCH][N];        // bias head output
__device__ float g_off[BATCH][N];         // bmap - mean*wmap (per column)
__device__ float g_smax[BATCH][N];        // column max of z = l*sparse
__device__ float g_sinv[BATCH][N];        // 1/sum(exp(z-max))
__device__ float g_L[BATCH][N][N];        // logits [keys n][queries m]  (256MB)
__device__ float g_psum[BATCH][32][N];    // per-row-tile column sums of L
__device__ float g_pmx[BATCH][16][N];     // partial online-softmax max
__device__ float g_psm[BATCH][16][N];     // partial online-softmax sum
__device__ float g_Ymid[BATCH][C][N];     // attention output before conv3x3

// ============================================================================
// K1: Q = q_w @ x + q_b ; V = v_w @ x + v_b   (1x1 convs as GEMM)
// ============================================================================
__global__ void k1_qv(const float* __restrict__ x,
                      const float* __restrict__ qw, const float* __restrict__ qb,
                      const float* __restrict__ vw, const float* __restrict__ vb) {
    const int b = blockIdx.y;
    const int which = blockIdx.z;
    const float* W = which ? vw : qw;
    const float* bias = which ? vb : qb;
    float* out = which ? &g_V[b][0][0] : &g_Q[b][0][0];
    const int n0 = blockIdx.x * 128;
    const float* xb = x + (size_t)b * C * N;

    __shared__ float As[16][128];
    __shared__ float Bs[16][128];
    const int tid = threadIdx.x;
    const int tx = tid & 15, ty = tid >> 4;

    float acc[8][8];
#pragma unroll
    for (int i = 0; i < 8; i++)
#pragma unroll
        for (int j = 0; j < 8; j++) acc[i][j] = 0.f;

    for (int k0 = 0; k0 < 128; k0 += 16) {
        {
            int o = tid >> 1;
            int kb = (tid & 1) * 8;
            float4 a0 = *(const float4*)(W + o * 128 + k0 + kb);
            float4 a1 = *(const float4*)(W + o * 128 + k0 + kb + 4);
            As[kb + 0][o] = a0.x; As[kb + 1][o] = a0.y; As[kb + 2][o] = a0.z; As[kb + 3][o] = a0.w;
            As[kb + 4][o] = a1.x; As[kb + 5][o] = a1.y; As[kb + 6][o] = a1.z; As[kb + 7][o] = a1.w;
        }
        {
            int kk = tid >> 4;
            int nn = (tid & 15) * 8;
            float4 b0 = *(const float4*)(xb + (size_t)(k0 + kk) * N + n0 + nn);
            float4 b1 = *(const float4*)(xb + (size_t)(k0 + kk) * N + n0 + nn + 4);
            *(float4*)&Bs[kk][nn] = b0;
            *(float4*)&Bs[kk][nn + 4] = b1;
        }
        __syncthreads();
#pragma unroll
        for (int kk = 0; kk < 16; kk++) {
            float ra[8], rb[8];
            *(float4*)&ra[0] = *(const float4*)&As[kk][ty * 8];
            *(float4*)&ra[4] = *(const float4*)&As[kk][ty * 8 + 4];
            *(float4*)&rb[0] = *(const float4*)&Bs[kk][tx * 8];
            *(float4*)&rb[4] = *(const float4*)&Bs[kk][tx * 8 + 4];
#pragma unroll
            for (int i = 0; i < 8; i++)
#pragma unroll
                for (int j = 0; j < 8; j++)
                    acc[i][j] = fmaf(ra[i], rb[j], acc[i][j]);
        }
        __syncthreads();
    }
#pragma unroll
    for (int i = 0; i < 8; i++) {
        int o = ty * 8 + i;
        float bo = bias[o];
        float4 r0, r1;
        r0.x = acc[i][0] + bo; r0.y = acc[i][1] + bo; r0.z = acc[i][2] + bo; r0.w = acc[i][3] + bo;
        r1.x = acc[i][4] + bo; r1.y = acc[i][5] + bo; r1.z = acc[i][6] + bo; r1.w = acc[i][7] + bo;
        *(float4*)(out + (size_t)o * N + n0 + tx * 8) = r0;
        *(float4*)(out + (size_t)o * N + n0 + tx * 8 + 4) = r1;
    }
}

// ============================================================================
// K2: per-token heads (weight map, bias map) + inverse key norm
// ============================================================================
__global__ void k2_heads(const float* __restrict__ lw1w, const float* __restrict__ lw1b,
                         const float* __restrict__ lw2w, const float* __restrict__ lw2b,
                         const float* __restrict__ bw1w, const float* __restrict__ bw1b,
                         const float* __restrict__ bw2w, const float* __restrict__ bw2b) {
    __shared__ float s_lw1[MID][C];
    __shared__ float s_bw1[MID][C];
    const int b = blockIdx.y;
    const int n = blockIdx.x * 256 + threadIdx.x;
    for (int e = threadIdx.x; e < MID * C; e += 256) {
        s_lw1[e / C][e % C] = lw1w[e];
        s_bw1[e / C][e % C] = bw1w[e];
    }
    __syncthreads();

    float hl[MID], hb[MID];
#pragma unroll
    for (int h = 0; h < MID; h++) { hl[h] = 0.f; hb[h] = 0.f; }
    float sq = 0.f;
#pragma unroll 4
    for (int c = 0; c < C; c++) {
        float q = g_Q[b][c][n];
        sq = fmaf(q, q, sq);
#pragma unroll
        for (int h = 0; h < MID; h++) {
            hl[h] = fmaf(s_lw1[h][c], q, hl[h]);
            hb[h] = fmaf(s_bw1[h][c], q, hb[h]);
        }
    }
    float wv = lw2b[0], bv = bw2b[0];
#pragma unroll
    for (int h = 0; h < MID; h++) {
        float t = hl[h] + lw1b[h];
        t = (t >= 0.f) ? t : 0.2f * t;
        wv = fmaf(lw2w[h], t, wv);
        float u = hb[h] + bw1b[h];
        u = (u >= 0.f) ? u : 0.2f * u;
        bv = fmaf(bw2w[h], u, bv);
    }
    g_wmap[b][n] = wv;
    g_bmap[b][n] = bv;
    g_invnorm[b][n] = 1.0f / fmaxf(sqrtf(sq), 1e-4f);
}

// ============================================================================
// K3: symmetric logits. Gram tile G = Q_tile(i)^T Q_tile(j), i<=j only (528 pairs)
//     write L[n][m]=G*inv[n] and (if i!=j) L[m][n]=G*inv[m]
//     also emit per-row-tile column sums into g_psum (feeds mean, no extra pass)
// ============================================================================
__global__ void k3_logits_sym() {
    const int b = blockIdx.y;
    // decode pair index -> (it, jt), it <= jt, 32x32 tiles
    int rem = blockIdx.x;
    int it = 0;
    while (rem >= 32 - it) { rem -= 32 - it; it++; }
    const int jt = it + rem;
    const int n0 = it * 128;
    const int m0 = jt * 128;

    __shared__ float As[16][128];
    __shared__ float Bs[16][128];
    const int tid = threadIdx.x;
    const int tx = tid & 15, ty = tid >> 4;

    float acc[8][8];
#pragma unroll
    for (int i = 0; i < 8; i++)
#pragma unroll
        for (int j = 0; j < 8; j++) acc[i][j] = 0.f;

    const int kk = tid >> 4;
    const int cc = (tid & 15) * 8;
    for (int k0 = 0; k0 < 128; k0 += 16) {
        float4 a0 = *(const float4*)&g_Q[b][k0 + kk][n0 + cc];
        float4 a1 = *(const float4*)&g_Q[b][k0 + kk][n0 + cc + 4];
        *(float4*)&As[kk][cc] = a0; *(float4*)&As[kk][cc + 4] = a1;
        float4 b0 = *(const float4*)&g_Q[b][k0 + kk][m0 + cc];
        float4 b1 = *(const float4*)&g_Q[b][k0 + kk][m0 + cc + 4];
        *(float4*)&Bs[kk][cc] = b0; *(float4*)&Bs[kk][cc + 4] = b1;
        __syncthreads();
#pragma unroll
        for (int k = 0; k < 16; k++) {
            float ra[8], rb[8];
            *(float4*)&ra[0] = *(const float4*)&As[k][ty * 8];
            *(float4*)&ra[4] = *(const float4*)&As[k][ty * 8 + 4];
            *(float4*)&rb[0] = *(const float4*)&Bs[k][tx * 8];
            *(float4*)&rb[4] = *(const float4*)&Bs[k][tx * 8 + 4];
#pragma unroll
            for (int i = 0; i < 8; i++)
#pragma unroll
                for (int j = 0; j < 8; j++)
                    acc[i][j] = fmaf(ra[i], rb[j], acc[i][j]);
        }
        __syncthreads();
    }

    float invn[8], invm[8];
#pragma unroll
    for (int i = 0; i < 8; i++) {
        invn[i] = g_invnorm[b][n0 + ty * 8 + i];
        invm[i] = g_invnorm[b][m0 + tx * 8 + i];
    }

    // normal write: L[n][m] = G * inv[n]
#pragma unroll
    for (int i = 0; i < 8; i++) {
        int n = n0 + ty * 8 + i;
        float inv = invn[i];
        float4 r0, r1;
        r0.x = acc[i][0] * inv; r0.y = acc[i][1] * inv; r0.z = acc[i][2] * inv; r0.w = acc[i][3] * inv;
        r1.x = acc[i][4] * inv; r1.y = acc[i][5] * inv; r1.z = acc[i][6] * inv; r1.w = acc[i][7] * inv;
        *(float4*)&g_L[b][n][m0 + tx * 8] = r0;
        *(float4*)&g_L[b][n][m0 + tx * 8 + 4] = r1;
    }
    // transposed write: L[m][n] = G * inv[m]
    if (it != jt) {
#pragma unroll
        for (int j = 0; j < 8; j++) {
            int m = m0 + tx * 8 + j;
            float iv = invm[j];
            float4 r0, r1;
            r0.x = acc[0][j] * iv; r0.y = acc[1][j] * iv; r0.z = acc[2][j] * iv; r0.w = acc[3][j] * iv;
            r1.x = acc[4][j] * iv; r1.y = acc[5][j] * iv; r1.z = acc[6][j] * iv; r1.w = acc[7][j] * iv;
            *(float4*)&g_L[b][m][n0 + ty * 8] = r0;
            *(float4*)&g_L[b][m][n0 + ty * 8 + 4] = r1;
        }
    }

    // column-sum partials (reuse As). Stage 1: rows tile it, cols range jt
    __syncthreads();
#pragma unroll
    for (int j = 0; j < 8; j++) {
        float s = 0.f;
#pragma unroll
        for (int i = 0; i < 8; i++) s = fmaf(acc[i][j], invn[i], s);
        As[ty][tx * 8 + j] = s;
    }
    __syncthreads();
    if (tid < 128) {
        float s = 0.f;
#pragma unroll
        for (int r = 0; r < 16; r++) s += As[r][tid];
        g_psum[b][it][m0 + tid] = s;
    }
    // Stage 2: rows tile jt, cols range it (transposed tile)
    if (it != jt) {
        __syncthreads();
#pragma unroll
        for (int i = 0; i < 8; i++) {
            float s = 0.f;
#pragma unroll
            for (int j = 0; j < 8; j++) s = fmaf(acc[i][j], invm[j], s);
            As[tx][ty * 8 + i] = s;
        }
        __syncthreads();
        if (tid < 128) {
            float s = 0.f;
#pragma unroll
            for (int r = 0; r < 16; r++) s += As[r][tid];
            g_psum[b][jt][n0 + tid] = s;
        }
    }
}

// ============================================================================
// K4b: partial online max/sum-exp of z = l*relu(l+off) over 256-row chunks.
// mean is rebuilt from g_psum per column (32 cheap loads), chunk 0 stores off.
// 4 independent accumulator chains per thread for MLP.
// ============================================================================
__global__ void k4b_partial() {
    const int b = blockIdx.z;
    const int chunk = blockIdx.y;
    const int m = blockIdx.x * 256 + threadIdx.x;

    float ps = 0.f;
#pragma unroll
    for (int t = 0; t < 32; t++) ps += g_psum[b][t][m];
    const float mean = ps * (1.0f / N);
    const float off = g_bmap[b][m] - mean * g_wmap[b][m];
    if (chunk == 0) g_off[b][m] = off;

    const int nbase = chunk * 256;
    float mx0 = -1e30f, mx1 = -1e30f, mx2 = -1e30f, mx3 = -1e30f;
    float s0 = 0.f, s1 = 0.f, s2 = 0.f, s3 = 0.f;

#define CHAIN(MX, S, L) { float sp = fmaxf((L) + off, 0.f); float z = (L) * sp; \
    if (z <= MX) { S += __expf(z - MX); } else { S = S * __expf(MX - z) + 1.f; MX = z; } }

#pragma unroll 2
    for (int r = 0; r < 256; r += 4) {
        float l0 = g_L[b][nbase + r + 0][m];
        float l1 = g_L[b][nbase + r + 1][m];
        float l2 = g_L[b][nbase + r + 2][m];
        float l3 = g_L[b][nbase + r + 3][m];
        CHAIN(mx0, s0, l0);
        CHAIN(mx1, s1, l1);
        CHAIN(mx2, s2, l2);
        CHAIN(mx3, s3, l3);
    }
#undef CHAIN
    // merge 4 chains
    float M = fmaxf(fmaxf(mx0, mx1), fmaxf(mx2, mx3));
    float S = s0 * __expf(mx0 - M) + s1 * __expf(mx1 - M)
            + s2 * __expf(mx2 - M) + s3 * __expf(mx3 - M);
    g_pmx[b][chunk][m] = M;
    g_psm[b][chunk][m] = S;
}

// K4c: merge 16 chunk partials -> smax, sinv
__global__ void k4c_final() {
    const int b = blockIdx.y;
    const int m = blockIdx.x * 256 + threadIdx.x;
    float M = g_pmx[b][0][m];
    float S = g_psm[b][0][m];
#pragma unroll
    for (int t = 1; t < 16; t++) {
        float m2 = g_pmx[b][t][m], s2 = g_psm[b][t][m];
        float Mn = fmaxf(M, m2);
        S = S * __expf(M - Mn) + s2 * __expf(m2 - Mn);
        M = Mn;
    }
    g_smax[b][m] = M;
    g_sinv[b][m] = 1.0f / S;
}

// ============================================================================
// K5: Y = V @ attn(L) -- attn on-the-fly; software-pipelined (reg prefetch)
// ============================================================================
__global__ void k5_out() {
    const int b = blockIdx.y;
    const int m0 = blockIdx.x * 128;

    __shared__ float As[16][128];
    __shared__ float Bs[16][128];
    __shared__ float p_off[128], p_mx[128], p_si[128];
    const int tid = threadIdx.x;
    const int tx = tid & 15, ty = tid >> 4;

    if (tid < 128) {
        int m = m0 + tid;
        p_off[tid] = g_off[b][m];
        p_mx[tid] = g_smax[b][m];
        p_si[tid] = g_sinv[b][m];
    }

    float acc[8][8];
#pragma unroll
    for (int i = 0; i < 8; i++)
#pragma unroll
        for (int j = 0; j < 8; j++) acc[i][j] = 0.f;

    const int ac = tid >> 1;
    const int akb = (tid & 1) * 8;
    const int bkk = tid >> 4;
    const int bmm = (tid & 15) * 8;

    // prefetch tile 0
    float av[8], lv[8];
    {
        float4 a0 = *(const float4*)&g_V[b][ac][akb];
        float4 a1 = *(const float4*)&g_V[b][ac][akb + 4];
        *(float4*)&av[0] = a0; *(float4*)&av[4] = a1;
        *(float4*)&lv[0] = *(const float4*)&g_L[b][bkk][m0 + bmm];
        *(float4*)&lv[4] = *(const float4*)&g_L[b][bkk][m0 + bmm + 4];
    }
    __syncthreads();   // p_off/p_mx/p_si ready

    for (int n0 = 0; n0 < N; n0 += 16) {
        // commit prefetched tile to smem (B gets the attn transform)
        As[akb + 0][ac] = av[0]; As[akb + 1][ac] = av[1];
        As[akb + 2][ac] = av[2]; As[akb + 3][ac] = av[3];
        As[akb + 4][ac] = av[4]; As[akb + 5][ac] = av[5];
        As[akb + 6][ac] = av[6]; As[akb + 7][ac] = av[7];
#pragma unroll
        for (int j = 0; j < 8; j++) {
            int m = bmm + j;
            float l = lv[j];
            float sp = fmaxf(l + p_off[m], 0.f);
            float a;
            if (sp > 0.f)
                a = fmaxf(__expf(l * sp - p_mx[m]) * p_si[m], 1e-8f);
            else
                a = __expf(-p_mx[m]) * p_si[m];  // z = 0 path, then mask -> 1e-8
            if (sp <= 0.f) a = 1e-8f;
            Bs[bkk][m] = a;
        }
        __syncthreads();

        // issue next tile loads (overlap with compute below)
        if (n0 + 16 < N) {
            float4 a0 = *(const float4*)&g_V[b][ac][n0 + 16 + akb];
            float4 a1 = *(const float4*)&g_V[b][ac][n0 + 16 + akb + 4];
            *(float4*)&av[0] = a0; *(float4*)&av[4] = a1;
            *(float4*)&lv[0] = *(const float4*)&g_L[b][n0 + 16 + bkk][m0 + bmm];
            *(float4*)&lv[4] = *(const float4*)&g_L[b][n0 + 16 + bkk][m0 + bmm + 4];
        }

#pragma unroll
        for (int k = 0; k < 16; k++) {
            float ra[8], rb[8];
            *(float4*)&ra[0] = *(const float4*)&As[k][ty * 8];
            *(float4*)&ra[4] = *(const float4*)&As[k][ty * 8 + 4];
            *(float4*)&rb[0] = *(const float4*)&Bs[k][tx * 8];
            *(float4*)&rb[4] = *(const float4*)&Bs[k][tx * 8 + 4];
#pragma unroll
            for (int i = 0; i < 8; i++)
#pragma unroll
                for (int j = 0; j < 8; j++)
                    acc[i][j] = fmaf(ra[i], rb[j], acc[i][j]);
        }
        __syncthreads();
    }
#pragma unroll
    for (int i = 0; i < 8; i++) {
        int c = ty * 8 + i;
        *(float4*)&g_Ymid[b][c][m0 + tx * 8] = *(float4*)&acc[i][0];
        *(float4*)&g_Ymid[b][c][m0 + tx * 8 + 4] = *(float4*)&acc[i][4];
    }
}

// ============================================================================
// K6: conv3x3(SAME) as 9 shifted GEMMs + bias + leaky + residual
// ============================================================================
__global__ void k6_conv(const float* __restrict__ linw, const float* __restrict__ linb,
                        const float* __restrict__ x, float* __restrict__ out) {
    const int b = blockIdx.y;
    const int p0 = blockIdx.x * 128;

    __shared__ float As[16][128];
    __shared__ float Bs[16][128];
    const int tid = threadIdx.x;
    const int tx = tid & 15, ty = tid >> 4;

    float acc[8][8];
#pragma unroll
    for (int i = 0; i < 8; i++)
#pragma unroll
        for (int j = 0; j < 8; j++) acc[i][j] = 0.f;

    const int ao = tid >> 1;
    const int akb = (tid & 1) * 8;
    const int bkk = tid >> 4;
    const int bpx = (tid & 15) * 8;

    for (int t = 0; t < 9; t++) {
        const int dh = t / 3 - 1, dw = t % 3 - 1;
        for (int i0 = 0; i0 < 128; i0 += 16) {
#pragma unroll
            for (int q = 0; q < 8; q++)
                As[akb + q][ao] = linw[(size_t)(ao * 128 + i0 + akb + q) * 9 + t];
#pragma unroll
            for (int q = 0; q < 8; q++) {
                int p = p0 + bpx + q;
                int h = p >> 6, w = p & 63;
                int hh = h + dh, ww = w + dw;
                float v = 0.f;
                if (hh >= 0 && hh < HW && ww >= 0 && ww < HW)
                    v = g_Ymid[b][i0 + bkk][(hh << 6) + ww];
                Bs[bkk][bpx + q] = v;
            }
            __syncthreads();
#pragma unroll
            for (int k = 0; k < 16; k++) {
                float ra[8], rb[8];
                *(float4*)&ra[0] = *(const float4*)&As[k][ty * 8];
                *(float4*)&ra[4] = *(const float4*)&As[k][ty * 8 + 4];
                *(float4*)&rb[0] = *(const float4*)&Bs[k][tx * 8];
                *(float4*)&rb[4] = *(const float4*)&Bs[k][tx * 8 + 4];
#pragma unroll
                for (int i = 0; i < 8; i++)
#pragma unroll
                    for (int j = 0; j < 8; j++)
                        acc[i][j] = fmaf(ra[i], rb[j], acc[i][j]);
            }
            __syncthreads();
        }
    }
#pragma unroll
    for (int i = 0; i < 8; i++) {
        int o = ty * 8 + i;
        float bo = linb[o];
        size_t base = ((size_t)b * C + o) * N + p0 + tx * 8;
#pragma unroll
        for (int j = 0; j < 8; j++) {
            float v = acc[i][j] + bo;
            v = (v >= 0.f) ? v : 0.2f * v;
            out[base + j] = v + x[base + j];
        }
    }
}

// ============================================================================
extern "C" void kernel_launch(void* const* d_in, const int* in_sizes, int n_in,
                              void* d_out, int out_size) {
    const float* x     = (const float*)d_in[0];
    const float* q_w   = (const float*)d_in[1];
    const float* q_b   = (const float*)d_in[2];
    const float* v_w   = (const float*)d_in[3];
    const float* v_b   = (const float*)d_in[4];
    const float* lw1_w = (const float*)d_in[5];
    const float* lw1_b = (const float*)d_in[6];
    const float* lw2_w = (const float*)d_in[7];
    const float* lw2_b = (const float*)d_in[8];
    const float* bw1_w = (const float*)d_in[9];
    const float* bw1_b = (const float*)d_in[10];
    const float* bw2_w = (const float*)d_in[11];
    const float* bw2_b = (const float*)d_in[12];
    const float* lin_w = (const float*)d_in[13];
    const float* lin_b = (const float*)d_in[14];
    float* out = (float*)d_out;

    k1_qv<<<dim3(N / 128, BATCH, 2), 256>>>(x, q_w, q_b, v_w, v_b);
    k2_heads<<<dim3(N / 256, BATCH), 256>>>(lw1_w, lw1_b, lw2_w, lw2_b,
                                            bw1_w, bw1_b, bw2_w, bw2_b);
    k3_logits_sym<<<dim3(528, BATCH), 256>>>();
    k4b_partial<<<dim3(16, 16, BATCH), 256>>>();
    k4c_final<<<dim3(16, BATCH), 256>>>();
    k5_out<<<dim3(N / 128, BATCH), 256>>>();
    k6_conv<<<dim3(N / 128, BATCH), 256>>>(lin_w, lin_b, x, out);
}